// round 3
// baseline (speedup 1.0000x reference)
#include <cuda_runtime.h>
#include <math.h>

// Problem dims (fixed by reference)
#define B   128
#define N   2048
#define H   768
#define H2  1536
#define S   16          // N-splits for pooling
#define NPS (N / S)     // 128 rows per split
#define FT  16          // features per gemm block
#define BH  64          // batch half per gemm block
#define LN_EPS 1e-5f

// Scratch (static device globals; no allocation allowed)
__device__ float g_partial[B * S * H];   // 6.3 MB
__device__ float g_pooled[B * H];        // 393 KB
__device__ float g_gh[B * H2];           // gelu(h) 786 KB

// ---------------------------------------------------------------------------
// Kernel 1: partial mean-pool. grid = (S, B), block = 192 threads (x float4).
// Reads 805 MB of v_emb exactly once, fully coalesced. 8 loads in flight
// per thread (MLP=8) to hide DRAM latency through wave transitions.
// ---------------------------------------------------------------------------
__global__ void __launch_bounds__(192) pool_partial(const float* __restrict__ v) {
    const int s = blockIdx.x;
    const int b = blockIdx.y;
    const int t = threadIdx.x;              // 0..191, 192*4 = 768 = H

    const float4* p = reinterpret_cast<const float4*>(
        v + ((size_t)b * N + (size_t)s * NPS) * H) + t;
    const int stride = H / 4;               // float4 stride per n

    float4 a0 = make_float4(0.f,0.f,0.f,0.f), a1 = a0, a2 = a0, a3 = a0;
    float4 a4 = a0, a5 = a0, a6 = a0, a7 = a0;

    #pragma unroll 1
    for (int n = 0; n < NPS; n += 8) {
        float4 x0 = p[(n + 0) * stride];
        float4 x1 = p[(n + 1) * stride];
        float4 x2 = p[(n + 2) * stride];
        float4 x3 = p[(n + 3) * stride];
        float4 x4 = p[(n + 4) * stride];
        float4 x5 = p[(n + 5) * stride];
        float4 x6 = p[(n + 6) * stride];
        float4 x7 = p[(n + 7) * stride];
        a0.x += x0.x; a0.y += x0.y; a0.z += x0.z; a0.w += x0.w;
        a1.x += x1.x; a1.y += x1.y; a1.z += x1.z; a1.w += x1.w;
        a2.x += x2.x; a2.y += x2.y; a2.z += x2.z; a2.w += x2.w;
        a3.x += x3.x; a3.y += x3.y; a3.z += x3.z; a3.w += x3.w;
        a4.x += x4.x; a4.y += x4.y; a4.z += x4.z; a4.w += x4.w;
        a5.x += x5.x; a5.y += x5.y; a5.z += x5.z; a5.w += x5.w;
        a6.x += x6.x; a6.y += x6.y; a6.z += x6.z; a6.w += x6.w;
        a7.x += x7.x; a7.y += x7.y; a7.z += x7.z; a7.w += x7.w;
    }
    float4 acc;
    acc.x = ((a0.x + a1.x) + (a2.x + a3.x)) + ((a4.x + a5.x) + (a6.x + a7.x));
    acc.y = ((a0.y + a1.y) + (a2.y + a3.y)) + ((a4.y + a5.y) + (a6.y + a7.y));
    acc.z = ((a0.z + a1.z) + (a2.z + a3.z)) + ((a4.z + a5.z) + (a6.z + a7.z));
    acc.w = ((a0.w + a1.w) + (a2.w + a3.w)) + ((a4.w + a5.w) + (a6.w + a7.w));

    float4* dst = reinterpret_cast<float4*>(g_partial + ((size_t)b * S + s) * H) + t;
    *dst = acc;
}

// ---------------------------------------------------------------------------
// Kernel 2: fold the S partial sums, scale by 1/N. grid = B, block = 192.
// ---------------------------------------------------------------------------
__global__ void __launch_bounds__(192) pool_reduce() {
    const int b = blockIdx.x;
    const int t = threadIdx.x;

    float4 acc = make_float4(0.f, 0.f, 0.f, 0.f);
    #pragma unroll
    for (int s = 0; s < S; s++) {
        float4 x = *(reinterpret_cast<const float4*>(g_partial + ((size_t)b * S + s) * H) + t);
        acc.x += x.x; acc.y += x.y; acc.z += x.z; acc.w += x.w;
    }
    const float inv = 1.0f / (float)N;
    acc.x *= inv; acc.y *= inv; acc.z *= inv; acc.w *= inv;
    *(reinterpret_cast<float4*>(g_pooled + (size_t)b * H) + t) = acc;
}

// ---------------------------------------------------------------------------
// Kernel 3: h = pooled @ W1 + b1, then exact GELU.
// grid = (H2/FT, B/BH) = (96, 2) = 192 blocks -> whole chip covered.
// 256 threads: each thread owns 1 feature x 4 batch rows.
// W1 (4.7 MB) still streamed from DRAM exactly twice total (once per b-half,
// L2-resident on the second) -- negligible vs compute.
// ---------------------------------------------------------------------------
__global__ void __launch_bounds__(256) gemm_gelu(const float* __restrict__ W1,
                                                 const float* __restrict__ b1) {
    __shared__ float sp[32][BH + 1];  // pooled^T k-tile: [k][b], padded
    __shared__ float sw[32][FT];      // W1 tile: [k][f]

    const int fbase = blockIdx.x * FT;
    const int bbase = blockIdx.y * BH;
    const int t = threadIdx.x;
    const int f = t & 15;           // feature within tile
    const int g = t >> 4;           // batch group (0..15), 4 rows each

    float acc[4];
    #pragma unroll
    for (int j = 0; j < 4; j++) acc[j] = 0.f;

    for (int kt = 0; kt < H; kt += 32) {
        // load pooled^T tile: 32k x 64b = 2048 floats
        #pragma unroll
        for (int i = t; i < 32 * BH; i += 256) {
            int bb = i >> 5, kk = i & 31;
            sp[kk][bb] = g_pooled[(bbase + bb) * H + kt + kk];
        }
        // load W1 tile: 32k x 16f = 512 floats
        #pragma unroll
        for (int i = t; i < 32 * FT; i += 256) {
            int ff = i & 15, kk = i >> 4;
            sw[kk][ff] = W1[(size_t)(kt + kk) * H2 + fbase + ff];
        }
        __syncthreads();

        #pragma unroll
        for (int k = 0; k < 32; k++) {
            float wv = sw[k][f];
            #pragma unroll
            for (int j = 0; j < 4; j++)
                acc[j] += sp[k][g * 4 + j] * wv;
        }
        __syncthreads();
    }

    #pragma unroll
    for (int j = 0; j < 4; j++) {
        int bb = bbase + g * 4 + j;
        float x = acc[j] + b1[fbase + f];
        // exact GELU (matches approximate=False): 0.5*x*(1+erf(x/sqrt(2)))
        float ge = 0.5f * x * (1.0f + erff(x * 0.70710678118654752f));
        g_gh[(size_t)bb * H2 + fbase + f] = ge;
    }
}

// ---------------------------------------------------------------------------
// Kernel 4: per-row LayerNorm + head dot + one-hot logits.
// grid = B, block = 512 (each thread owns 3 of the 1536 features).
// Output layout: d_out[0..B)        = pred   (B,1 flattened)
//                d_out[B..B+B*16)   = logits (B,16 flattened)
// ---------------------------------------------------------------------------
__global__ void __launch_bounds__(512) ln_head(const float* __restrict__ gamma,
                                               const float* __restrict__ beta,
                                               const float* __restrict__ W2,
                                               const float* __restrict__ b2,
                                               float* __restrict__ out) {
    const int b = blockIdx.x;
    const int t = threadIdx.x;          // 0..511
    const float* row = g_gh + (size_t)b * H2;

    float x0 = row[t];
    float x1 = row[t + 512];
    float x2 = row[t + 1024];

    float s  = x0 + x1 + x2;
    float sq = x0 * x0 + x1 * x1 + x2 * x2;

    __shared__ float sA[16], sB[16];
    #pragma unroll
    for (int o = 16; o; o >>= 1) {
        s  += __shfl_xor_sync(0xFFFFFFFFu, s,  o);
        sq += __shfl_xor_sync(0xFFFFFFFFu, sq, o);
    }
    int w = t >> 5, l = t & 31;
    if (l == 0) { sA[w] = s; sB[w] = sq; }
    __syncthreads();
    if (t < 32) {
        float a  = (l < 16) ? sA[l] : 0.f;
        float bq = (l < 16) ? sB[l] : 0.f;
        #pragma unroll
        for (int o = 8; o; o >>= 1) {
            a  += __shfl_xor_sync(0xFFFFFFFFu, a,  o);
            bq += __shfl_xor_sync(0xFFFFFFFFu, bq, o);
        }
        if (l == 0) { sA[0] = a; sB[0] = bq; }
    }
    __syncthreads();

    const float mu  = sA[0] * (1.0f / (float)H2);
    const float var = sB[0] * (1.0f / (float)H2) - mu * mu;
    const float rstd = rsqrtf(var + LN_EPS);

    __syncthreads();   // protect sA/sB reuse below

    float y0 = (x0 - mu) * rstd * gamma[t]        + beta[t];
    float y1 = (x1 - mu) * rstd * gamma[t + 512]  + beta[t + 512];
    float y2 = (x2 - mu) * rstd * gamma[t + 1024] + beta[t + 1024];

    float local = y0 * W2[t] + y1 * W2[t + 512] + y2 * W2[t + 1024];
    #pragma unroll
    for (int o = 16; o; o >>= 1)
        local += __shfl_xor_sync(0xFFFFFFFFu, local, o);
    if (l == 0) sA[w] = local;
    __syncthreads();
    if (t < 32) {
        float a = (l < 16) ? sA[l] : 0.f;
        #pragma unroll
        for (int o = 8; o; o >>= 1)
            a += __shfl_xor_sync(0xFFFFFFFFu, a, o);
        if (l == 0) sA[0] = a;
    }
    __syncthreads();

    const float pred = sA[0] + b2[0];

    if (t == 0) out[b] = pred;

    // one-hot logits: round-half-even to match jnp.round, clamp [0,15]
    if (t < 16) {
        float r = rintf(pred);
        r = fminf(fmaxf(r, 0.f), 15.f);
        int aid = (int)r;
        out[B + b * 16 + t] = (t == aid) ? 1.0f : 0.0f;
    }
}

// ---------------------------------------------------------------------------
extern "C" void kernel_launch(void* const* d_in, const int* in_sizes, int n_in,
                              void* d_out, int out_size) {
    const float* v_emb = (const float*)d_in[0];  // [B,N,H]
    const float* W1    = (const float*)d_in[1];  // [H,2H]
    const float* b1    = (const float*)d_in[2];  // [2H]
    const float* gamma = (const float*)d_in[3];  // [2H]
    const float* beta  = (const float*)d_in[4];  // [2H]
    const float* W2    = (const float*)d_in[5];  // [2H,1]
    const float* b2    = (const float*)d_in[6];  // [1]
    float* out = (float*)d_out;

    pool_partial<<<dim3(S, B), 192>>>(v_emb);
    pool_reduce<<<B, 192>>>();
    gemm_gelu<<<dim3(H2 / FT, B / BH), 256>>>(W1, b1);
    ln_head<<<B, 512>>>(gamma, beta, W2, b2, out);
}

// round 5
// speedup vs baseline: 1.0937x; 1.0937x over previous
#include <cuda_runtime.h>
#include <math.h>

// Problem dims (fixed by reference)
#define B   128
#define N   2048
#define H   768
#define H2  1536
#define S   16          // N-splits for pooling
#define NPS (N / S)     // 128 rows per split
#define KS  3           // k-splits for gemm
#define KPS (H / KS)    // 256 k per split
#define LN_EPS 1e-5f

// Scratch (static device globals; no allocation allowed)
__device__ float g_partial[B * S * H];     // 6.3 MB
__device__ float g_pooled[B * H];          // 393 KB
__device__ float g_hp[KS * B * H2];        // gemm k-split partials, 2.4 MB
__device__ float g_gh[B * H2];             // gelu(h) 786 KB

// ---------------------------------------------------------------------------
// Kernel 1: partial mean-pool. grid = (S, B), block = 192 threads (x float4).
// Reads 805 MB of v_emb exactly once, fully coalesced, MLP=8.
// ---------------------------------------------------------------------------
__global__ void __launch_bounds__(192) pool_partial(const float* __restrict__ v) {
    const int s = blockIdx.x;
    const int b = blockIdx.y;
    const int t = threadIdx.x;              // 0..191, 192*4 = 768 = H

    const float4* p = reinterpret_cast<const float4*>(
        v + ((size_t)b * N + (size_t)s * NPS) * H) + t;
    const int stride = H / 4;               // float4 stride per n

    float4 a0 = make_float4(0.f,0.f,0.f,0.f), a1 = a0, a2 = a0, a3 = a0;
    float4 a4 = a0, a5 = a0, a6 = a0, a7 = a0;

    #pragma unroll 1
    for (int n = 0; n < NPS; n += 8) {
        float4 x0 = p[(n + 0) * stride];
        float4 x1 = p[(n + 1) * stride];
        float4 x2 = p[(n + 2) * stride];
        float4 x3 = p[(n + 3) * stride];
        float4 x4 = p[(n + 4) * stride];
        float4 x5 = p[(n + 5) * stride];
        float4 x6 = p[(n + 6) * stride];
        float4 x7 = p[(n + 7) * stride];
        a0.x += x0.x; a0.y += x0.y; a0.z += x0.z; a0.w += x0.w;
        a1.x += x1.x; a1.y += x1.y; a1.z += x1.z; a1.w += x1.w;
        a2.x += x2.x; a2.y += x2.y; a2.z += x2.z; a2.w += x2.w;
        a3.x += x3.x; a3.y += x3.y; a3.z += x3.z; a3.w += x3.w;
        a4.x += x4.x; a4.y += x4.y; a4.z += x4.z; a4.w += x4.w;
        a5.x += x5.x; a5.y += x5.y; a5.z += x5.z; a5.w += x5.w;
        a6.x += x6.x; a6.y += x6.y; a6.z += x6.z; a6.w += x6.w;
        a7.x += x7.x; a7.y += x7.y; a7.z += x7.z; a7.w += x7.w;
    }
    float4 acc;
    acc.x = ((a0.x + a1.x) + (a2.x + a3.x)) + ((a4.x + a5.x) + (a6.x + a7.x));
    acc.y = ((a0.y + a1.y) + (a2.y + a3.y)) + ((a4.y + a5.y) + (a6.y + a7.y));
    acc.z = ((a0.z + a1.z) + (a2.z + a3.z)) + ((a4.z + a5.z) + (a6.z + a7.z));
    acc.w = ((a0.w + a1.w) + (a2.w + a3.w)) + ((a4.w + a5.w) + (a6.w + a7.w));

    float4* dst = reinterpret_cast<float4*>(g_partial + ((size_t)b * S + s) * H) + t;
    *dst = acc;
}

// ---------------------------------------------------------------------------
// Kernel 2: fold the S partial sums, scale by 1/N. grid = B, block = 192.
// ---------------------------------------------------------------------------
__global__ void __launch_bounds__(192) pool_reduce() {
    const int b = blockIdx.x;
    const int t = threadIdx.x;

    float4 acc = make_float4(0.f, 0.f, 0.f, 0.f);
    #pragma unroll
    for (int s = 0; s < S; s++) {
        float4 x = *(reinterpret_cast<const float4*>(g_partial + ((size_t)b * S + s) * H) + t);
        acc.x += x.x; acc.y += x.y; acc.z += x.z; acc.w += x.w;
    }
    const float inv = 1.0f / (float)N;
    acc.x *= inv; acc.y *= inv; acc.z *= inv; acc.w *= inv;
    *(reinterpret_cast<float4*>(g_pooled + (size_t)b * H) + t) = acc;
}

// ---------------------------------------------------------------------------
// Kernel 3: k-split GEMM partials.  h_partial = pooled[:, ks] @ W1[ks, :].
// grid = (24 f-tiles, 2 b-tiles, 3 k-splits) = 144 blocks (~= 148 SMs).
// Block: 256 threads (tx=f 0..15, ty=b 0..15), thread tile 4f x 4b.
// Inner loop: 2x LDS.128 -> 16 FFMA (FFMA-bound, ~9 us chip-wide).
// ---------------------------------------------------------------------------
#define GF 64   // features per block tile
#define GB 64   // batch per block tile
#define GK 32   // k per smem tile
#define SPLD 68 // padded sp row (4-float pad: 16B-aligned rows, 4-way store conflicts only)

__global__ void __launch_bounds__(256) gemm_part(const float* __restrict__ W1) {
    __shared__ float sp[GK][SPLD];    // pooled^T tile: [k][b]
    __shared__ float sw[GK][GF];      // W1 tile:       [k][f]

    const int fbase = blockIdx.x * GF;
    const int bbase = blockIdx.y * GB;
    const int k0    = blockIdx.z * KPS;
    const int t  = threadIdx.x;
    const int tx = t & 15;            // f group
    const int ty = t >> 4;            // b group

    float acc[4][4];                  // [bi][fi]
    #pragma unroll
    for (int i = 0; i < 4; i++)
        #pragma unroll
        for (int j = 0; j < 4; j++) acc[i][j] = 0.f;

    for (int kt = 0; kt < KPS; kt += GK) {
        // sp load: coalesced along k, transposed into [k][b] (padded rows)
        #pragma unroll
        for (int i = t; i < GB * GK; i += 256) {
            int bb = i >> 5, kk = i & 31;
            sp[kk][bb] = g_pooled[(bbase + bb) * H + k0 + kt + kk];
        }
        // sw load: coalesced along f
        #pragma unroll
        for (int i = t; i < GK * GF; i += 256) {
            int kk = i >> 6, ff = i & 63;
            sw[kk][ff] = W1[(size_t)(k0 + kt + kk) * H2 + fbase + ff];
        }
        __syncthreads();

        #pragma unroll
        for (int kk = 0; kk < GK; kk++) {
            float4 wv = *reinterpret_cast<const float4*>(&sw[kk][tx * 4]);
            float4 pv = *reinterpret_cast<const float4*>(&sp[kk][ty * 4]);
            const float pb[4] = {pv.x, pv.y, pv.z, pv.w};
            const float wf[4] = {wv.x, wv.y, wv.z, wv.w};
            #pragma unroll
            for (int bi = 0; bi < 4; bi++)
                #pragma unroll
                for (int fi = 0; fi < 4; fi++)
                    acc[bi][fi] += pb[bi] * wf[fi];
        }
        __syncthreads();
    }

    // write partials (float4 along f)
    float* dst = g_hp + (size_t)blockIdx.z * B * H2;
    #pragma unroll
    for (int bi = 0; bi < 4; bi++) {
        int row = bbase + ty * 4 + bi;
        float4 o = make_float4(acc[bi][0], acc[bi][1], acc[bi][2], acc[bi][3]);
        *reinterpret_cast<float4*>(dst + (size_t)row * H2 + fbase + tx * 4) = o;
    }
}

// ---------------------------------------------------------------------------
// Kernel 4: fold the KS gemm partials, add bias, exact GELU.
// grid = B*H2/(256*4) = 192 blocks, 256 threads x float4.
// ---------------------------------------------------------------------------
__global__ void __launch_bounds__(256) gelu_reduce(const float* __restrict__ b1) {
    const int idx = (blockIdx.x * 256 + threadIdx.x) * 4;   // element index in [B*H2)
    const int f = idx % H2;

    float4 a = *reinterpret_cast<const float4*>(g_hp + idx);
    float4 c = *reinterpret_cast<const float4*>(g_hp + B * H2 + idx);
    float4 d = *reinterpret_cast<const float4*>(g_hp + 2 * B * H2 + idx);
    float4 bb = *reinterpret_cast<const float4*>(b1 + f);

    float x0 = a.x + c.x + d.x + bb.x;
    float x1 = a.y + c.y + d.y + bb.y;
    float x2 = a.z + c.z + d.z + bb.z;
    float x3 = a.w + c.w + d.w + bb.w;

    const float r2 = 0.70710678118654752f;
    float4 o;
    o.x = 0.5f * x0 * (1.0f + erff(x0 * r2));
    o.y = 0.5f * x1 * (1.0f + erff(x1 * r2));
    o.z = 0.5f * x2 * (1.0f + erff(x2 * r2));
    o.w = 0.5f * x3 * (1.0f + erff(x3 * r2));
    *reinterpret_cast<float4*>(g_gh + idx) = o;
}

// ---------------------------------------------------------------------------
// Kernel 5: per-row LayerNorm + head dot + one-hot logits.
// grid = B, block = 384 (each thread owns one float4 of the 1536 features).
// Output layout: d_out[0..B)        = pred   (B,1 flattened)
//                d_out[B..B+B*16)   = logits (B,16 flattened)
// ---------------------------------------------------------------------------
__global__ void __launch_bounds__(384) ln_head(const float* __restrict__ gamma,
                                               const float* __restrict__ beta,
                                               const float* __restrict__ W2,
                                               const float* __restrict__ b2,
                                               float* __restrict__ out) {
    const int b = blockIdx.x;
    const int t = threadIdx.x;          // 0..383
    const int w = t >> 5, l = t & 31;   // 12 warps

    float4 x = *reinterpret_cast<const float4*>(g_gh + (size_t)b * H2 + t * 4);

    float s  = (x.x + x.y) + (x.z + x.w);
    float sq = (x.x * x.x + x.y * x.y) + (x.z * x.z + x.w * x.w);

    __shared__ float sA[12], sB[12];
    #pragma unroll
    for (int o = 16; o; o >>= 1) {
        s  += __shfl_xor_sync(0xFFFFFFFFu, s,  o);
        sq += __shfl_xor_sync(0xFFFFFFFFu, sq, o);
    }
    if (l == 0) { sA[w] = s; sB[w] = sq; }
    __syncthreads();
    if (t < 32) {
        float a  = (l < 12) ? sA[l] : 0.f;
        float bq = (l < 12) ? sB[l] : 0.f;
        #pragma unroll
        for (int o = 8; o; o >>= 1) {
            a  += __shfl_xor_sync(0xFFFFFFFFu, a,  o);
            bq += __shfl_xor_sync(0xFFFFFFFFu, bq, o);
        }
        if (l == 0) { sA[0] = a; sB[0] = bq; }
    }
    __syncthreads();

    const float mu  = sA[0] * (1.0f / (float)H2);
    const float var = sB[0] * (1.0f / (float)H2) - mu * mu;
    const float rstd = rsqrtf(var + LN_EPS);

    __syncthreads();   // protect sA/sB reuse below

    float4 gm = *reinterpret_cast<const float4*>(gamma + t * 4);
    float4 bt = *reinterpret_cast<const float4*>(beta  + t * 4);
    float4 w2 = *reinterpret_cast<const float4*>(W2    + t * 4);

    float y0 = (x.x - mu) * rstd * gm.x + bt.x;
    float y1 = (x.y - mu) * rstd * gm.y + bt.y;
    float y2 = (x.z - mu) * rstd * gm.z + bt.z;
    float y3 = (x.w - mu) * rstd * gm.w + bt.w;

    float local = (y0 * w2.x + y1 * w2.y) + (y2 * w2.z + y3 * w2.w);
    #pragma unroll
    for (int o = 16; o; o >>= 1)
        local += __shfl_xor_sync(0xFFFFFFFFu, local, o);
    if (l == 0) sA[w] = local;
    __syncthreads();
    if (t < 32) {
        float a = (l < 12) ? sA[l] : 0.f;
        #pragma unroll
        for (int o = 8; o; o >>= 1)
            a += __shfl_xor_sync(0xFFFFFFFFu, a, o);
        if (l == 0) sA[0] = a;
    }
    __syncthreads();

    const float pred = sA[0] + b2[0];

    if (t == 0) out[b] = pred;

    // one-hot logits: round-half-even to match jnp.round, clamp [0,15]
    if (t < 16) {
        float r = rintf(pred);
        r = fminf(fmaxf(r, 0.f), 15.f);
        int aid = (int)r;
        out[B + b * 16 + t] = (t == aid) ? 1.0f : 0.0f;
    }
}

// ---------------------------------------------------------------------------
extern "C" void kernel_launch(void* const* d_in, const int* in_sizes, int n_in,
                              void* d_out, int out_size) {
    const float* v_emb = (const float*)d_in[0];  // [B,N,H]
    const float* W1    = (const float*)d_in[1];  // [H,2H]
    const float* b1    = (const float*)d_in[2];  // [2H]
    const float* gamma = (const float*)d_in[3];  // [2H]
    const float* beta  = (const float*)d_in[4];  // [2H]
    const float* W2    = (const float*)d_in[5];  // [2H,1]
    const float* b2    = (const float*)d_in[6];  // [1]
    float* out = (float*)d_out;

    pool_partial<<<dim3(S, B), 192>>>(v_emb);
    pool_reduce<<<B, 192>>>();
    gemm_part<<<dim3(H2 / GF, B / GB, KS), 256>>>(W1);
    gelu_reduce<<<(B * H2) / (256 * 4), 256>>>(b1);
    ln_head<<<B, 384>>>(gamma, beta, W2, b2, out);
}

// round 6
// speedup vs baseline: 1.1761x; 1.0753x over previous
#include <cuda_runtime.h>
#include <math.h>

// Problem dims (fixed by reference)
#define B   128
#define N   2048
#define H   768
#define H2  1536
#define S   8           // N-splits for pooling (1024 blocks = one resident wave)
#define NPS (N / S)     // 256 rows per split
#define KS  3           // k-splits for gemm
#define KPS (H / KS)    // 256 k per split
#define LN_EPS 1e-5f

// Scratch (static device globals; no allocation allowed)
__device__ float g_partial[B * S * H];     // 3.1 MB
__device__ float g_pooled[B * H];          // 393 KB
__device__ float g_hp[KS * B * H2];        // gemm k-split partials, 2.4 MB

// ---------------------------------------------------------------------------
// Kernel 1: partial mean-pool. grid = (S=8, B) = 1024 blocks, 192 thr each.
// unroll 4 keeps regs <= 48 so __launch_bounds__(192,7) holds 7 blocks/SM:
// 1036 resident blocks -> entire grid is ONE wave, no transitions, no tail.
// Reads 805 MB of v_emb exactly once, fully coalesced.
// ---------------------------------------------------------------------------
__global__ void __launch_bounds__(192, 7) pool_partial(const float* __restrict__ v) {
    const int s = blockIdx.x;
    const int b = blockIdx.y;
    const int t = threadIdx.x;              // 0..191, 192*4 = 768 = H

    const float4* p = reinterpret_cast<const float4*>(
        v + ((size_t)b * N + (size_t)s * NPS) * H) + t;
    const int stride = H / 4;               // float4 stride per n

    float4 a0 = make_float4(0.f,0.f,0.f,0.f), a1 = a0, a2 = a0, a3 = a0;

    #pragma unroll 1
    for (int n = 0; n < NPS; n += 4) {
        float4 x0 = p[(n + 0) * stride];
        float4 x1 = p[(n + 1) * stride];
        float4 x2 = p[(n + 2) * stride];
        float4 x3 = p[(n + 3) * stride];
        a0.x += x0.x; a0.y += x0.y; a0.z += x0.z; a0.w += x0.w;
        a1.x += x1.x; a1.y += x1.y; a1.z += x1.z; a1.w += x1.w;
        a2.x += x2.x; a2.y += x2.y; a2.z += x2.z; a2.w += x2.w;
        a3.x += x3.x; a3.y += x3.y; a3.z += x3.z; a3.w += x3.w;
    }
    float4 acc;
    acc.x = (a0.x + a1.x) + (a2.x + a3.x);
    acc.y = (a0.y + a1.y) + (a2.y + a3.y);
    acc.z = (a0.z + a1.z) + (a2.z + a3.z);
    acc.w = (a0.w + a1.w) + (a2.w + a3.w);

    float4* dst = reinterpret_cast<float4*>(g_partial + ((size_t)b * S + s) * H) + t;
    *dst = acc;
}

// ---------------------------------------------------------------------------
// Kernel 2: fold the S partial sums, scale by 1/N. grid = B, block = 192.
// ---------------------------------------------------------------------------
__global__ void __launch_bounds__(192) pool_reduce() {
    const int b = blockIdx.x;
    const int t = threadIdx.x;

    float4 acc = make_float4(0.f, 0.f, 0.f, 0.f);
    #pragma unroll
    for (int s = 0; s < S; s++) {
        float4 x = *(reinterpret_cast<const float4*>(g_partial + ((size_t)b * S + s) * H) + t);
        acc.x += x.x; acc.y += x.y; acc.z += x.z; acc.w += x.w;
    }
    const float inv = 1.0f / (float)N;
    acc.x *= inv; acc.y *= inv; acc.z *= inv; acc.w *= inv;
    *(reinterpret_cast<float4*>(g_pooled + (size_t)b * H) + t) = acc;
}

// ---------------------------------------------------------------------------
// Kernel 3: k-split GEMM partials.  h_partial = pooled[:, ks] @ W1[ks, :].
// grid = (24 f-tiles, 2 b-tiles, 3 k-splits) = 144 blocks (~= 148 SMs).
// Block: 256 threads (tx=f 0..15, ty=b 0..15), thread tile 4f x 4b.
// ---------------------------------------------------------------------------
#define GF 64   // features per block tile
#define GB 64   // batch per block tile
#define GK 32   // k per smem tile
#define SPLD 68 // padded sp row

__global__ void __launch_bounds__(256) gemm_part(const float* __restrict__ W1) {
    __shared__ float sp[GK][SPLD];    // pooled^T tile: [k][b]
    __shared__ float sw[GK][GF];      // W1 tile:       [k][f]

    const int fbase = blockIdx.x * GF;
    const int bbase = blockIdx.y * GB;
    const int k0    = blockIdx.z * KPS;
    const int t  = threadIdx.x;
    const int tx = t & 15;            // f group
    const int ty = t >> 4;            // b group

    float acc[4][4];                  // [bi][fi]
    #pragma unroll
    for (int i = 0; i < 4; i++)
        #pragma unroll
        for (int j = 0; j < 4; j++) acc[i][j] = 0.f;

    for (int kt = 0; kt < KPS; kt += GK) {
        #pragma unroll
        for (int i = t; i < GB * GK; i += 256) {
            int bb = i >> 5, kk = i & 31;
            sp[kk][bb] = g_pooled[(bbase + bb) * H + k0 + kt + kk];
        }
        #pragma unroll
        for (int i = t; i < GK * GF; i += 256) {
            int kk = i >> 6, ff = i & 63;
            sw[kk][ff] = W1[(size_t)(k0 + kt + kk) * H2 + fbase + ff];
        }
        __syncthreads();

        #pragma unroll
        for (int kk = 0; kk < GK; kk++) {
            float4 wv = *reinterpret_cast<const float4*>(&sw[kk][tx * 4]);
            float4 pv = *reinterpret_cast<const float4*>(&sp[kk][ty * 4]);
            const float pb[4] = {pv.x, pv.y, pv.z, pv.w};
            const float wf[4] = {wv.x, wv.y, wv.z, wv.w};
            #pragma unroll
            for (int bi = 0; bi < 4; bi++)
                #pragma unroll
                for (int fi = 0; fi < 4; fi++)
                    acc[bi][fi] += pb[bi] * wf[fi];
        }
        __syncthreads();
    }

    float* dst = g_hp + (size_t)blockIdx.z * B * H2;
    #pragma unroll
    for (int bi = 0; bi < 4; bi++) {
        int row = bbase + ty * 4 + bi;
        float4 o = make_float4(acc[bi][0], acc[bi][1], acc[bi][2], acc[bi][3]);
        *reinterpret_cast<float4*>(dst + (size_t)row * H2 + fbase + tx * 4) = o;
    }
}

// ---------------------------------------------------------------------------
// Kernel 4: fused (k-partial fold + bias + exact GELU) -> LayerNorm -> head
// -> one-hot logits.  grid = B, block = 384 (one float4 of H2 per thread).
// Output layout: d_out[0..B)        = pred   (B,1 flattened)
//                d_out[B..B+B*16)   = logits (B,16 flattened)
// ---------------------------------------------------------------------------
__global__ void __launch_bounds__(384) ln_head(const float* __restrict__ b1,
                                               const float* __restrict__ gamma,
                                               const float* __restrict__ beta,
                                               const float* __restrict__ W2,
                                               const float* __restrict__ b2,
                                               float* __restrict__ out) {
    const int b = blockIdx.x;
    const int t = threadIdx.x;          // 0..383
    const int w = t >> 5, l = t & 31;   // 12 warps

    const size_t off = (size_t)b * H2 + t * 4;
    float4 pa = *reinterpret_cast<const float4*>(g_hp + off);
    float4 pc = *reinterpret_cast<const float4*>(g_hp + (size_t)B * H2 + off);
    float4 pd = *reinterpret_cast<const float4*>(g_hp + 2 * (size_t)B * H2 + off);
    float4 bb = *reinterpret_cast<const float4*>(b1 + t * 4);

    // fold k-splits + bias, exact GELU (matches approximate=False)
    const float r2 = 0.70710678118654752f;
    float h0 = pa.x + pc.x + pd.x + bb.x;
    float h1 = pa.y + pc.y + pd.y + bb.y;
    float h2 = pa.z + pc.z + pd.z + bb.z;
    float h3 = pa.w + pc.w + pd.w + bb.w;
    float4 x;
    x.x = 0.5f * h0 * (1.0f + erff(h0 * r2));
    x.y = 0.5f * h1 * (1.0f + erff(h1 * r2));
    x.z = 0.5f * h2 * (1.0f + erff(h2 * r2));
    x.w = 0.5f * h3 * (1.0f + erff(h3 * r2));

    float s  = (x.x + x.y) + (x.z + x.w);
    float sq = (x.x * x.x + x.y * x.y) + (x.z * x.z + x.w * x.w);

    __shared__ float sA[12], sB[12];
    #pragma unroll
    for (int o = 16; o; o >>= 1) {
        s  += __shfl_xor_sync(0xFFFFFFFFu, s,  o);
        sq += __shfl_xor_sync(0xFFFFFFFFu, sq, o);
    }
    if (l == 0) { sA[w] = s; sB[w] = sq; }
    __syncthreads();
    if (t < 32) {
        float a  = (l < 12) ? sA[l] : 0.f;
        float bq = (l < 12) ? sB[l] : 0.f;
        #pragma unroll
        for (int o = 8; o; o >>= 1) {
            a  += __shfl_xor_sync(0xFFFFFFFFu, a,  o);
            bq += __shfl_xor_sync(0xFFFFFFFFu, bq, o);
        }
        if (l == 0) { sA[0] = a; sB[0] = bq; }
    }
    __syncthreads();

    const float mu  = sA[0] * (1.0f / (float)H2);
    const float var = sB[0] * (1.0f / (float)H2) - mu * mu;
    const float rstd = rsqrtf(var + LN_EPS);

    __syncthreads();   // protect sA/sB reuse below

    float4 gm = *reinterpret_cast<const float4*>(gamma + t * 4);
    float4 bt = *reinterpret_cast<const float4*>(beta  + t * 4);
    float4 w2 = *reinterpret_cast<const float4*>(W2    + t * 4);

    float y0 = (x.x - mu) * rstd * gm.x + bt.x;
    float y1 = (x.y - mu) * rstd * gm.y + bt.y;
    float y2 = (x.z - mu) * rstd * gm.z + bt.z;
    float y3 = (x.w - mu) * rstd * gm.w + bt.w;

    float local = (y0 * w2.x + y1 * w2.y) + (y2 * w2.z + y3 * w2.w);
    #pragma unroll
    for (int o = 16; o; o >>= 1)
        local += __shfl_xor_sync(0xFFFFFFFFu, local, o);
    if (l == 0) sA[w] = local;
    __syncthreads();
    if (t < 32) {
        float a = (l < 12) ? sA[l] : 0.f;
        #pragma unroll
        for (int o = 8; o; o >>= 1)
            a += __shfl_xor_sync(0xFFFFFFFFu, a, o);
        if (l == 0) sA[0] = a;
    }
    __syncthreads();

    const float pred = sA[0] + b2[0];

    if (t == 0) out[b] = pred;

    // one-hot logits: round-half-even to match jnp.round, clamp [0,15]
    if (t < 16) {
        float r = rintf(pred);
        r = fminf(fmaxf(r, 0.f), 15.f);
        int aid = (int)r;
        out[B + b * 16 + t] = (t == aid) ? 1.0f : 0.0f;
    }
}

// ---------------------------------------------------------------------------
extern "C" void kernel_launch(void* const* d_in, const int* in_sizes, int n_in,
                              void* d_out, int out_size) {
    const float* v_emb = (const float*)d_in[0];  // [B,N,H]
    const float* W1    = (const float*)d_in[1];  // [H,2H]
    const float* b1    = (const float*)d_in[2];  // [2H]
    const float* gamma = (const float*)d_in[3];  // [2H]
    const float* beta  = (const float*)d_in[4];  // [2H]
    const float* W2    = (const float*)d_in[5];  // [2H,1]
    const float* b2    = (const float*)d_in[6];  // [1]
    float* out = (float*)d_out;

    pool_partial<<<dim3(S, B), 192>>>(v_emb);
    pool_reduce<<<B, 192>>>();
    gemm_part<<<dim3(H2 / GF, B / GB, KS), 256>>>(W1);
    ln_head<<<B, 384>>>(b1, gamma, beta, W2, b2, out);
}

// round 8
// speedup vs baseline: 1.2102x; 1.0290x over previous
#include <cuda_runtime.h>
#include <math.h>

// Problem dims (fixed by reference)
#define B   128
#define N   2048
#define H   768
#define H2  1536
#define S   8           // N-splits for pooling (1024 blocks = one resident wave)
#define NPS (N / S)     // 256 rows per split
#define KS  3           // k-splits for gemm
#define KPS (H / KS)    // 256 k per split
#define NBLK (S * B)    // 1024 pool blocks (must ALL be resident: 148*7=1036)
#define LN_EPS 1e-5f

// Scratch (static device globals; no allocation allowed)
__device__ float g_partial[B * S * H];     // 3.1 MB
__device__ float g_pooled[B * H];          // 393 KB
__device__ float g_hp[KS * B * H2];        // gemm k-split partials, 2.4 MB

// grid-barrier state (persistent across graph replays; epoch-based)
__device__ unsigned g_bar_count = 0u;
__device__ unsigned g_bar_gen   = 0u;

// ---------------------------------------------------------------------------
// Kernel 1: fused mean-pool (partial + fold). grid = (S=8, B) = 1024 blocks,
// 192 threads. __launch_bounds__(192,7) guarantees 7 blocks/SM (regs<=48,
// no meaningful smem) -> all 1024 blocks resident -> grid barrier is safe.
// Phase 1: every block sums its 256-row slice (streaming __ldcs loads).
// Barrier. Phase 2: the 128 blocks with blockIdx.x==0 fold the 8 partials.
// ---------------------------------------------------------------------------
__global__ void __launch_bounds__(192, 7) pool_fused(const float* __restrict__ v) {
    const int s = blockIdx.x;
    const int b = blockIdx.y;
    const int t = threadIdx.x;              // 0..191, 192*4 = 768 = H

    // read barrier epoch before arriving anywhere (all blocks see same value)
    unsigned base_gen = 0;
    if (t == 0) base_gen = *(volatile unsigned*)&g_bar_gen;

    const float4* p = reinterpret_cast<const float4*>(
        v + ((size_t)b * N + (size_t)s * NPS) * H) + t;
    const int stride = H / 4;               // float4 stride per n

    float4 a0 = make_float4(0.f,0.f,0.f,0.f), a1 = a0, a2 = a0, a3 = a0;

    #pragma unroll 1
    for (int n = 0; n < NPS; n += 4) {
        float4 x0 = __ldcs(p + (n + 0) * stride);
        float4 x1 = __ldcs(p + (n + 1) * stride);
        float4 x2 = __ldcs(p + (n + 2) * stride);
        float4 x3 = __ldcs(p + (n + 3) * stride);
        a0.x += x0.x; a0.y += x0.y; a0.z += x0.z; a0.w += x0.w;
        a1.x += x1.x; a1.y += x1.y; a1.z += x1.z; a1.w += x1.w;
        a2.x += x2.x; a2.y += x2.y; a2.z += x2.z; a2.w += x2.w;
        a3.x += x3.x; a3.y += x3.y; a3.z += x3.z; a3.w += x3.w;
    }
    float4 acc;
    acc.x = (a0.x + a1.x) + (a2.x + a3.x);
    acc.y = (a0.y + a1.y) + (a2.y + a3.y);
    acc.z = (a0.z + a1.z) + (a2.z + a3.z);
    acc.w = (a0.w + a1.w) + (a2.w + a3.w);

    *(reinterpret_cast<float4*>(g_partial + ((size_t)b * S + s) * H) + t) = acc;

    // ---- grid barrier (all 1024 blocks resident by construction) ----
    __syncthreads();
    if (t == 0) {
        const unsigned target = base_gen + 1u;
        __threadfence();
        unsigned arr = atomicAdd(&g_bar_count, 1u);
        if (arr == NBLK - 1u) {
            g_bar_count = 0u;
            __threadfence();
            *(volatile unsigned*)&g_bar_gen = target;
        } else {
            while ((int)(*(volatile unsigned*)&g_bar_gen - target) < 0)
                __nanosleep(64);
        }
        __threadfence();
    }
    __syncthreads();

    // ---- phase 2: fold S partials, scale by 1/N (128 blocks participate) ----
    if (s == 0) {
        float4 r = make_float4(0.f, 0.f, 0.f, 0.f);
        #pragma unroll
        for (int ss = 0; ss < S; ss++) {
            float4 x = *(reinterpret_cast<const float4*>(
                g_partial + ((size_t)b * S + ss) * H) + t);
            r.x += x.x; r.y += x.y; r.z += x.z; r.w += x.w;
        }
        const float inv = 1.0f / (float)N;
        r.x *= inv; r.y *= inv; r.z *= inv; r.w *= inv;
        *(reinterpret_cast<float4*>(g_pooled + (size_t)b * H) + t) = r;
    }
}

// ---------------------------------------------------------------------------
// Kernel 2: k-split GEMM partials.  h_partial = pooled[:, ks] @ W1[ks, :].
// grid = (24 f-tiles, 2 b-tiles, 3 k-splits) = 144 blocks (~= 148 SMs).
// Block: 256 threads (tx=f 0..15, ty=b 0..15), thread tile 4f x 4b.
// ---------------------------------------------------------------------------
#define GF 64   // features per block tile
#define GB 64   // batch per block tile
#define GK 32   // k per smem tile
#define SPLD 68 // padded sp row

__global__ void __launch_bounds__(256) gemm_part(const float* __restrict__ W1) {
    __shared__ float sp[GK][SPLD];    // pooled^T tile: [k][b]
    __shared__ float sw[GK][GF];      // W1 tile:       [k][f]

    const int fbase = blockIdx.x * GF;
    const int bbase = blockIdx.y * GB;
    const int k0    = blockIdx.z * KPS;
    const int t  = threadIdx.x;
    const int tx = t & 15;            // f group
    const int ty = t >> 4;            // b group

    float acc[4][4];                  // [bi][fi]
    #pragma unroll
    for (int i = 0; i < 4; i++)
        #pragma unroll
        for (int j = 0; j < 4; j++) acc[i][j] = 0.f;

    for (int kt = 0; kt < KPS; kt += GK) {
        #pragma unroll
        for (int i = t; i < GB * GK; i += 256) {
            int bb = i >> 5, kk = i & 31;
            sp[kk][bb] = g_pooled[(bbase + bb) * H + k0 + kt + kk];
        }
        #pragma unroll
        for (int i = t; i < GK * GF; i += 256) {
            int kk = i >> 6, ff = i & 63;
            sw[kk][ff] = W1[(size_t)(k0 + kt + kk) * H2 + fbase + ff];
        }
        __syncthreads();

        #pragma unroll
        for (int kk = 0; kk < GK; kk++) {
            float4 wv = *reinterpret_cast<const float4*>(&sw[kk][tx * 4]);
            float4 pv = *reinterpret_cast<const float4*>(&sp[kk][ty * 4]);
            const float pb[4] = {pv.x, pv.y, pv.z, pv.w};
            const float wf[4] = {wv.x, wv.y, wv.z, wv.w};
            #pragma unroll
            for (int bi = 0; bi < 4; bi++)
                #pragma unroll
                for (int fi = 0; fi < 4; fi++)
                    acc[bi][fi] += pb[bi] * wf[fi];
        }
        __syncthreads();
    }

    float* dst = g_hp + (size_t)blockIdx.z * B * H2;
    #pragma unroll
    for (int bi = 0; bi < 4; bi++) {
        int row = bbase + ty * 4 + bi;
        float4 o = make_float4(acc[bi][0], acc[bi][1], acc[bi][2], acc[bi][3]);
        *reinterpret_cast<float4*>(dst + (size_t)row * H2 + fbase + tx * 4) = o;
    }
}

// ---------------------------------------------------------------------------
// Kernel 3: fused (k-partial fold + bias + exact GELU) -> LayerNorm -> head
// -> one-hot logits.  grid = B, block = 384 (one float4 of H2 per thread).
// Output layout: d_out[0..B)        = pred   (B,1 flattened)
//                d_out[B..B+B*16)   = logits (B,16 flattened)
// ---------------------------------------------------------------------------
__global__ void __launch_bounds__(384) ln_head(const float* __restrict__ b1,
                                               const float* __restrict__ gamma,
                                               const float* __restrict__ beta,
                                               const float* __restrict__ W2,
                                               const float* __restrict__ b2,
                                               float* __restrict__ out) {
    const int b = blockIdx.x;
    const int t = threadIdx.x;          // 0..383
    const int w = t >> 5, l = t & 31;   // 12 warps

    const size_t off = (size_t)b * H2 + t * 4;
    float4 pa = *reinterpret_cast<const float4*>(g_hp + off);
    float4 pc = *reinterpret_cast<const float4*>(g_hp + (size_t)B * H2 + off);
    float4 pd = *reinterpret_cast<const float4*>(g_hp + 2 * (size_t)B * H2 + off);
    float4 bb = *reinterpret_cast<const float4*>(b1 + t * 4);

    // fold k-splits + bias, exact GELU (matches approximate=False)
    const float r2 = 0.70710678118654752f;
    float h0 = pa.x + pc.x + pd.x + bb.x;
    float h1 = pa.y + pc.y + pd.y + bb.y;
    float h2 = pa.z + pc.z + pd.z + bb.z;
    float h3 = pa.w + pc.w + pd.w + bb.w;
    float4 x;
    x.x = 0.5f * h0 * (1.0f + erff(h0 * r2));
    x.y = 0.5f * h1 * (1.0f + erff(h1 * r2));
    x.z = 0.5f * h2 * (1.0f + erff(h2 * r2));
    x.w = 0.5f * h3 * (1.0f + erff(h3 * r2));

    float s  = (x.x + x.y) + (x.z + x.w);
    float sq = (x.x * x.x + x.y * x.y) + (x.z * x.z + x.w * x.w);

    __shared__ float sA[12], sB[12];
    #pragma unroll
    for (int o = 16; o; o >>= 1) {
        s  += __shfl_xor_sync(0xFFFFFFFFu, s,  o);
        sq += __shfl_xor_sync(0xFFFFFFFFu, sq, o);
    }
    if (l == 0) { sA[w] = s; sB[w] = sq; }
    __syncthreads();
    if (t < 32) {
        float a  = (l < 12) ? sA[l] : 0.f;
        float bq = (l < 12) ? sB[l] : 0.f;
        #pragma unroll
        for (int o = 8; o; o >>= 1) {
            a  += __shfl_xor_sync(0xFFFFFFFFu, a,  o);
            bq += __shfl_xor_sync(0xFFFFFFFFu, bq, o);
        }
        if (l == 0) { sA[0] = a; sB[0] = bq; }
    }
    __syncthreads();

    const float mu  = sA[0] * (1.0f / (float)H2);
    const float var = sB[0] * (1.0f / (float)H2) - mu * mu;
    const float rstd = rsqrtf(var + LN_EPS);

    __syncthreads();   // protect sA/sB reuse below

    float4 gm = *reinterpret_cast<const float4*>(gamma + t * 4);
    float4 bt = *reinterpret_cast<const float4*>(beta  + t * 4);
    float4 w2 = *reinterpret_cast<const float4*>(W2    + t * 4);

    float y0 = (x.x - mu) * rstd * gm.x + bt.x;
    float y1 = (x.y - mu) * rstd * gm.y + bt.y;
    float y2 = (x.z - mu) * rstd * gm.z + bt.z;
    float y3 = (x.w - mu) * rstd * gm.w + bt.w;

    float local = (y0 * w2.x + y1 * w2.y) + (y2 * w2.z + y3 * w2.w);
    #pragma unroll
    for (int o = 16; o; o >>= 1)
        local += __shfl_xor_sync(0xFFFFFFFFu, local, o);
    if (l == 0) sA[w] = local;
    __syncthreads();
    if (t < 32) {
        float a = (l < 12) ? sA[l] : 0.f;
        #pragma unroll
        for (int o = 8; o; o >>= 1)
            a += __shfl_xor_sync(0xFFFFFFFFu, a, o);
        if (l == 0) sA[0] = a;
    }
    __syncthreads();

    const float pred = sA[0] + b2[0];

    if (t == 0) out[b] = pred;

    // one-hot logits: round-half-even to match jnp.round, clamp [0,15]
    if (t < 16) {
        float r = rintf(pred);
        r = fminf(fmaxf(r, 0.f), 15.f);
        int aid = (int)r;
        out[B + b * 16 + t] = (t == aid) ? 1.0f : 0.0f;
    }
}

// ---------------------------------------------------------------------------
extern "C" void kernel_launch(void* const* d_in, const int* in_sizes, int n_in,
                              void* d_out, int out_size) {
    const float* v_emb = (const float*)d_in[0];  // [B,N,H]
    const float* W1    = (const float*)d_in[1];  // [H,2H]
    const float* b1    = (const float*)d_in[2];  // [2H]
    const float* gamma = (const float*)d_in[3];  // [2H]
    const float* beta  = (const float*)d_in[4];  // [2H]
    const float* W2    = (const float*)d_in[5];  // [2H,1]
    const float* b2    = (const float*)d_in[6];  // [1]
    float* out = (float*)d_out;

    pool_fused<<<dim3(S, B), 192>>>(v_emb);
    gemm_part<<<dim3(H2 / GF, B / GB, KS), 256>>>(W1);
    ln_head<<<B, 384>>>(b1, gamma, beta, W2, b2, out);
}